// round 3
// baseline (speedup 1.0000x reference)
#include <cuda_runtime.h>
#include <cstdint>

// ---------------------------------------------------------------------------
// Problem constants
// ---------------------------------------------------------------------------
#define BB   2
#define LL   2048
#define DM   512
#define HH   8
#define KT   5            // kernel taps
#define HW   64           // head width
#define MTOT (BB*LL)                  // 4096 rows
#define NKV_ (HH*KT*HW)               // 2560 rows each for k and v
#define NTOT (DM + 2*NKV_)            // 5632
#define KBASE (DM)                    // 512
#define VBASE (DM + NKV_)             // 3072
#define KD   512                      // GEMM K dim (always D_MODEL)

// ---------------------------------------------------------------------------
// Device scratch
// ---------------------------------------------------------------------------
__device__ float g_PROJ[(size_t)MTOT * NTOT];     // 92.3 MB  projections
__device__ float g_ATTN[(size_t)MTOT * DM];       //  8.4 MB  fp32 attn output

// ---------------------------------------------------------------------------
// Helpers
// ---------------------------------------------------------------------------
__device__ __forceinline__ float to_tf32(float x) {
    uint32_t u = __float_as_uint(x), r;
    asm("cvt.rna.tf32.f32 %0, %1;" : "=r"(r) : "r"(u));
    return __uint_as_float(r);
}

__device__ __forceinline__ void mma_tf32(float d[4], const uint32_t a[4], const uint32_t b[2]) {
    asm volatile(
        "mma.sync.aligned.m16n8k8.row.col.f32.tf32.tf32.f32 "
        "{%0,%1,%2,%3}, {%4,%5,%6,%7}, {%8,%9}, {%0,%1,%2,%3};\n"
        : "+f"(d[0]), "+f"(d[1]), "+f"(d[2]), "+f"(d[3])
        : "r"(a[0]), "r"(a[1]), "r"(a[2]), "r"(a[3]), "r"(b[0]), "r"(b[1]));
}

#define CP_ASYNC16(smem32, gptr) \
    asm volatile("cp.async.cg.shared.global [%0], [%1], 16;\n" :: "r"(smem32), "l"(gptr))

// ---------------------------------------------------------------------------
// GEMM: C[M][n0:n0+BN] = A[M][512] * B[N][512]^T (+bias), tf32 mma.sync.
// A, B raw fp32; tf32 conversion (rna) in registers after LDS.
// SPLIT: hi/lo tf32 decomposition, 3 MMAs -> ~fp32 accuracy.
// 512 threads = 16 warps (4x4), CTA tile 128x128, warp tile 32x32, BK=16.
// ---------------------------------------------------------------------------
#define BM 128
#define BN 128
#define BK 16
#define SK 20      // smem row stride (conflict-free)

template <bool SPLIT, bool HAS_BIAS>
__global__ __launch_bounds__(512, 1) void gemm_tf32(
    const float* __restrict__ A, const float* __restrict__ B,
    float* __restrict__ C, int ldc,
    const float* __restrict__ bias)
{
    __shared__ float As[2][BM * SK];
    __shared__ float Bs[2][BN * SK];

    const int n0  = blockIdx.x * BN;
    const int m0  = blockIdx.y * BM;
    const int tid = threadIdx.x;
    const int warp = tid >> 5, lane = tid & 31;
    const int wm = (warp >> 2) * 32;   // 0,32,64,96
    const int wn = (warp & 3) * 32;    // 0,32,64,96
    const int g  = lane >> 2, t = lane & 3;

    float acc[2][4][4];
    #pragma unroll
    for (int mt = 0; mt < 2; mt++)
        #pragma unroll
        for (int nt = 0; nt < 4; nt++)
            #pragma unroll
            for (int i = 0; i < 4; i++) acc[mt][nt][i] = 0.f;

    const float* Ab = A + (size_t)m0 * KD;
    const float* Bb = B + (size_t)n0 * KD;

    // one 16B cp.async per thread per array per stage (512 thr = 128 rows x 4)
    const int lrow = tid >> 2;
    const int lcol = (tid & 3) * 4;

    auto load_stage = [&](int s, int k0) {
        uint32_t sa = (uint32_t)__cvta_generic_to_shared(&As[s][lrow * SK + lcol]);
        CP_ASYNC16(sa, Ab + (size_t)lrow * KD + k0 + lcol);
        uint32_t sb = (uint32_t)__cvta_generic_to_shared(&Bs[s][lrow * SK + lcol]);
        CP_ASYNC16(sb, Bb + (size_t)lrow * KD + k0 + lcol);
        asm volatile("cp.async.commit_group;\n" ::);
    };

    const int NKt = KD / BK;   // 32
    load_stage(0, 0);

    for (int kt = 0; kt < NKt; ++kt) {
        if (kt + 1 < NKt) {
            load_stage((kt + 1) & 1, (kt + 1) * BK);
            asm volatile("cp.async.wait_group 1;\n" ::);
        } else {
            asm volatile("cp.async.wait_group 0;\n" ::);
        }
        __syncthreads();

        const float* as = As[kt & 1];
        const float* bs = Bs[kt & 1];

        #pragma unroll
        for (int ks = 0; ks < 2; ++ks) {
            const int kb = ks * 8;
            uint32_t ahi[2][4], bhi[4][2];
            uint32_t alo[2][4], blo[4][2];

            #pragma unroll
            for (int mt = 0; mt < 2; mt++) {
                int r = wm + mt * 16 + g;
                float a0 = as[(r    ) * SK + kb + t    ];
                float a1 = as[(r + 8) * SK + kb + t    ];
                float a2 = as[(r    ) * SK + kb + t + 4];
                float a3 = as[(r + 8) * SK + kb + t + 4];
                float h0 = to_tf32(a0), h1 = to_tf32(a1), h2 = to_tf32(a2), h3 = to_tf32(a3);
                ahi[mt][0] = __float_as_uint(h0); ahi[mt][1] = __float_as_uint(h1);
                ahi[mt][2] = __float_as_uint(h2); ahi[mt][3] = __float_as_uint(h3);
                if (SPLIT) {
                    alo[mt][0] = __float_as_uint(to_tf32(a0 - h0));
                    alo[mt][1] = __float_as_uint(to_tf32(a1 - h1));
                    alo[mt][2] = __float_as_uint(to_tf32(a2 - h2));
                    alo[mt][3] = __float_as_uint(to_tf32(a3 - h3));
                }
            }
            #pragma unroll
            for (int nt = 0; nt < 4; nt++) {
                int n = wn + nt * 8 + g;
                float b0 = bs[n * SK + kb + t    ];
                float b1 = bs[n * SK + kb + t + 4];
                float h0 = to_tf32(b0), h1 = to_tf32(b1);
                bhi[nt][0] = __float_as_uint(h0); bhi[nt][1] = __float_as_uint(h1);
                if (SPLIT) {
                    blo[nt][0] = __float_as_uint(to_tf32(b0 - h0));
                    blo[nt][1] = __float_as_uint(to_tf32(b1 - h1));
                }
            }
            #pragma unroll
            for (int mt = 0; mt < 2; mt++)
                #pragma unroll
                for (int nt = 0; nt < 4; nt++) {
                    if (SPLIT) {
                        mma_tf32(acc[mt][nt], ahi[mt], blo[nt]);
                        mma_tf32(acc[mt][nt], alo[mt], bhi[nt]);
                    }
                    mma_tf32(acc[mt][nt], ahi[mt], bhi[nt]);
                }
        }
        __syncthreads();
    }

    // Epilogue: c0:(g,2t) c1:(g,2t+1) c2:(g+8,2t) c3:(g+8,2t+1)
    #pragma unroll
    for (int mt = 0; mt < 2; mt++) {
        int r = m0 + wm + mt * 16 + g;
        #pragma unroll
        for (int nt = 0; nt < 4; nt++) {
            int c = n0 + wn + nt * 8 + 2 * t;
            float b0 = 0.f, b1 = 0.f;
            if (HAS_BIAS) { b0 = bias[c]; b1 = bias[c + 1]; }
            *(float2*)&C[(size_t)(r    ) * ldc + c] = make_float2(acc[mt][nt][0] + b0, acc[mt][nt][1] + b1);
            *(float2*)&C[(size_t)(r + 8) * ldc + c] = make_float2(acc[mt][nt][2] + b0, acc[mt][nt][3] + b1);
        }
    }
}

// ---------------------------------------------------------------------------
// K2: attention. One warp per (b,l,h). 5-tap gather from PROJ, softmax,
// weighted V sum, /sqrt(64) -> fp32 ATTN (no rounding; K3 is split-tf32).
// Out-of-range taps: content zero => k/v collapse to biases.
// ---------------------------------------------------------------------------
__global__ __launch_bounds__(256) void attn_kernel(const float* __restrict__ qb,
                                                   const float* __restrict__ kb,
                                                   const float* __restrict__ vb) {
    int w    = (blockIdx.x * blockDim.x + threadIdx.x) >> 5;
    int lane = threadIdx.x & 31;
    if (w >= MTOT * HH) return;

    int h   = w & 7;
    int row = w >> 3;                 // = b*LL + l
    int l   = row & (LL - 1);
    int b   = row >> 11;
    int d   = 1 << (h & 3);           // dilations {1,2,4,8,1,2,4,8}

    const float* P = g_PROJ;
    size_t rq = (size_t)row * NTOT;
    int qoff = h * HW;
    float q0 = P[rq + qoff + lane]      + qb[qoff + lane];
    float q1 = P[rq + qoff + lane + 32] + qb[qoff + lane + 32];

    float lg[KT], v0[KT], v1[KT];
    #pragma unroll
    for (int kk = 0; kk < KT; ++kk) {
        int sl   = l + (kk - 2) * d;
        int kidx = (h * KT + kk) * HW;
        float kv0, kv1;
        if (sl >= 0 && sl < LL) {
            size_t rr = (size_t)(b * LL + sl) * NTOT;
            kv0    = P[rr + KBASE + kidx + lane]      + kb[kidx + lane];
            kv1    = P[rr + KBASE + kidx + lane + 32] + kb[kidx + lane + 32];
            v0[kk] = P[rr + VBASE + kidx + lane]      + vb[kidx + lane];
            v1[kk] = P[rr + VBASE + kidx + lane + 32] + vb[kidx + lane + 32];
        } else {
            kv0    = kb[kidx + lane];      kv1    = kb[kidx + lane + 32];
            v0[kk] = vb[kidx + lane];      v1[kk] = vb[kidx + lane + 32];
        }
        float p = q0 * kv0 + q1 * kv1;
        #pragma unroll
        for (int s = 16; s > 0; s >>= 1) p += __shfl_xor_sync(0xffffffffu, p, s);
        lg[kk] = p;
    }

    float mx = lg[0];
    #pragma unroll
    for (int kk = 1; kk < KT; ++kk) mx = fmaxf(mx, lg[kk]);
    float e[KT], se = 0.f;
    #pragma unroll
    for (int kk = 0; kk < KT; ++kk) { e[kk] = __expf(lg[kk] - mx); se += e[kk]; }
    float inv = 1.f / se;

    float a0 = 0.f, a1 = 0.f;
    #pragma unroll
    for (int kk = 0; kk < KT; ++kk) { a0 += e[kk] * v0[kk]; a1 += e[kk] * v1[kk]; }
    a0 *= inv * 0.125f;   // / sqrt(HEAD_W)
    a1 *= inv * 0.125f;

    g_ATTN[(size_t)row * DM + qoff + lane]      = a0;
    g_ATTN[(size_t)row * DM + qoff + lane + 32] = a1;
}

// ---------------------------------------------------------------------------
// Launch
// ---------------------------------------------------------------------------
extern "C" void kernel_launch(void* const* d_in, const int* in_sizes, int n_in,
                              void* d_out, int out_size) {
    const float* x   = (const float*)d_in[0];
    const float* q_w = (const float*)d_in[1];
    const float* q_b = (const float*)d_in[2];
    const float* k_w = (const float*)d_in[3];
    const float* k_b = (const float*)d_in[4];
    const float* v_w = (const float*)d_in[5];
    const float* v_b = (const float*)d_in[6];
    const float* o_w = (const float*)d_in[7];
    const float* o_b = (const float*)d_in[8];

    float *PROJ, *ATTN;
    cudaGetSymbolAddress((void**)&PROJ, g_PROJ);
    cudaGetSymbolAddress((void**)&ATTN, g_ATTN);

    // K1: PROJ[4096, 5632] = x @ [q_w; k_w; v_w]^T, raw weights, 3 slices
    gemm_tf32<false, false><<<dim3(DM  / BN, MTOT / BM), 512>>>(x, q_w, PROJ,         NTOT, nullptr);
    gemm_tf32<false, false><<<dim3(NKV_ / BN, MTOT / BM), 512>>>(x, k_w, PROJ + KBASE, NTOT, nullptr);
    gemm_tf32<false, false><<<dim3(NKV_ / BN, MTOT / BM), 512>>>(x, v_w, PROJ + VBASE, NTOT, nullptr);

    // K2: attention -> ATTN[4096, 512] (fp32)
    attn_kernel<<<(MTOT * HH * 32) / 256, 256>>>(q_b, k_b, v_b);

    // K3: OUT = ATTN @ o_w^T + o_b, split-tf32 (~fp32 accuracy)
    gemm_tf32<true, true><<<dim3(DM / BN, MTOT / BM), 512>>>(ATTN, o_w, (float*)d_out, DM, o_b);
}

// round 4
// speedup vs baseline: 2.2865x; 2.2865x over previous
#include <cuda_runtime.h>
#include <cuda_fp16.h>
#include <cstdint>

// ---------------------------------------------------------------------------
// Problem constants
// ---------------------------------------------------------------------------
#define BB   2
#define LL   2048
#define DM   512
#define HH   8
#define KT   5            // kernel taps
#define HW   64           // head width
#define MTOT (BB*LL)                  // 4096 rows
#define NKV_ (HH*KT*HW)               // 2560 rows each for k and v
#define NTOT (DM + 2*NKV_)            // 5632
#define KBASE (DM)                    // 512
#define VBASE (DM + NKV_)             // 3072
#define KD   512                      // GEMM K dim (always D_MODEL)

// ---------------------------------------------------------------------------
// Device scratch
// ---------------------------------------------------------------------------
__device__ __half g_Xh  [(size_t)MTOT * KD];      //  4.2 MB  fp16 x
__device__ __half g_Wh  [(size_t)NTOT * KD];      //  5.8 MB  fp16 [q;k;v] weights
__device__ __half g_OWh [(size_t)DM * KD];        //  0.5 MB  fp16 o_w
__device__ float  g_PROJ[(size_t)MTOT * NTOT];    // 92.3 MB  fp32 projections
__device__ __half g_ATTN[(size_t)MTOT * DM];      //  4.2 MB  fp16 attn output

// ---------------------------------------------------------------------------
// Helpers
// ---------------------------------------------------------------------------
__device__ __forceinline__ void ldm_x4(uint32_t& r0, uint32_t& r1, uint32_t& r2, uint32_t& r3,
                                       const void* p) {
    uint32_t a = (uint32_t)__cvta_generic_to_shared(p);
    asm volatile("ldmatrix.sync.aligned.m8n8.x4.shared.b16 {%0,%1,%2,%3}, [%4];"
                 : "=r"(r0), "=r"(r1), "=r"(r2), "=r"(r3) : "r"(a));
}

__device__ __forceinline__ void mma_fp16(float d[4], const uint32_t a[4], const uint32_t b[2]) {
    asm volatile(
        "mma.sync.aligned.m16n8k16.row.col.f32.f16.f16.f32 "
        "{%0,%1,%2,%3}, {%4,%5,%6,%7}, {%8,%9}, {%0,%1,%2,%3};\n"
        : "+f"(d[0]), "+f"(d[1]), "+f"(d[2]), "+f"(d[3])
        : "r"(a[0]), "r"(a[1]), "r"(a[2]), "r"(a[3]), "r"(b[0]), "r"(b[1]));
}

#define CP_ASYNC16(smem_ptr, gptr) \
    asm volatile("cp.async.cg.shared.global [%0], [%1], 16;\n" \
                 :: "r"((uint32_t)__cvta_generic_to_shared(smem_ptr)), "l"(gptr))

// ---------------------------------------------------------------------------
// K0: convert x, concat(q_w,k_w,v_w), o_w to fp16
// ---------------------------------------------------------------------------
#define NX_  (MTOT*KD)                 // 2097152
#define NQW_ (DM*KD)                   //  262144
#define NKW_ (NKV_*KD)                 // 1310720
#define NW_  (NQW_ + 2*NKW_)           // 2883584
#define PREP_TOT (NX_ + NW_ + NQW_)    // 5242880

__global__ void prep_kernel(const float* __restrict__ x,
                            const float* __restrict__ qw,
                            const float* __restrict__ kw,
                            const float* __restrict__ vw,
                            const float* __restrict__ ow) {
    int i = blockIdx.x * blockDim.x + threadIdx.x;
    if (i >= PREP_TOT) return;
    if (i < NX_) {
        g_Xh[i] = __float2half_rn(x[i]);
    } else {
        int j = i - NX_;
        if (j < NW_) {
            float v;
            if (j < NQW_)             v = qw[j];
            else if (j < NQW_ + NKW_) v = kw[j - NQW_];
            else                      v = vw[j - NQW_ - NKW_];
            g_Wh[j] = __float2half_rn(v);
        } else {
            g_OWh[j - NW_] = __float2half_rn(ow[j - NW_]);
        }
    }
}

// ---------------------------------------------------------------------------
// fp16 GEMM: C[M][n0:n0+BN] = A[M][512] * B[N][512]^T (+bias), fp32 accum.
// 256 threads = 8 warps (2x4), CTA tile 128x128, warp tile 64x32,
// BK=32 fp16, 2-stage cp.async, ldmatrix fragments.
// smem rows padded to 80B (stride 40 fp16): 5*16B coprime 8 => ldmatrix
// 8-row shots hit 8 distinct 16B banks (conflict-free).
// ---------------------------------------------------------------------------
#define BM 128
#define BN 128
#define BKH 32
#define SKH 40

template <bool HAS_BIAS>
__global__ __launch_bounds__(256, 2) void gemm_fp16(
    const __half* __restrict__ A, const __half* __restrict__ B,
    float* __restrict__ C, int ldc, const float* __restrict__ bias)
{
    __shared__ __half As[2][BM * SKH];   // 10240 B per stage-pair half
    __shared__ __half Bs[2][BN * SKH];   // total 40960 B

    const int n0  = blockIdx.x * BN;
    const int m0  = blockIdx.y * BM;
    const int tid = threadIdx.x;
    const int warp = tid >> 5, lane = tid & 31;
    const int wm = (warp >> 2) * 64;   // 0 or 64
    const int wn = (warp & 3) * 32;    // 0,32,64,96
    const int g  = lane >> 2, t = lane & 3;

    float acc[4][4][4];
    #pragma unroll
    for (int mt = 0; mt < 4; mt++)
        #pragma unroll
        for (int nt = 0; nt < 4; nt++)
            #pragma unroll
            for (int i = 0; i < 4; i++) acc[mt][nt][i] = 0.f;

    const __half* Ab = A + (size_t)m0 * KD;
    const __half* Bb = B + (size_t)n0 * KD;

    // stage load: 128 rows x 64B per array; 512 chunks of 16B; 2 per thread
    auto load_stage = [&](int s, int k0) {
        #pragma unroll
        for (int it = 0; it < 2; ++it) {
            int idx = tid + 256 * it;
            int row = idx >> 2;
            int c   = (idx & 3) * 8;          // fp16 offset, 16B granule
            CP_ASYNC16(&As[s][row * SKH + c], Ab + (size_t)row * KD + k0 + c);
            CP_ASYNC16(&Bs[s][row * SKH + c], Bb + (size_t)row * KD + k0 + c);
        }
        asm volatile("cp.async.commit_group;\n" ::);
    };

    const int NKt = KD / BKH;   // 16
    load_stage(0, 0);

    // ldmatrix lane->address components
    const int rowA  = lane & 15;
    const int kselA = ((lane >> 4) & 1) * 8;
    const int rowB  = lane & 7;
    const int nselB = ((lane >> 4) & 1) * 8;
    const int kselB = ((lane >> 3) & 1) * 8;

    for (int kt = 0; kt < NKt; ++kt) {
        if (kt + 1 < NKt) {
            load_stage((kt + 1) & 1, (kt + 1) * BKH);
            asm volatile("cp.async.wait_group 1;\n" ::);
        } else {
            asm volatile("cp.async.wait_group 0;\n" ::);
        }
        __syncthreads();

        const __half* as = As[kt & 1];
        const __half* bs = Bs[kt & 1];

        #pragma unroll
        for (int ch = 0; ch < 2; ++ch) {
            const int kb = ch * 16;
            uint32_t af[4][4], bf[4][2];
            #pragma unroll
            for (int mt = 0; mt < 4; mt++)
                ldm_x4(af[mt][0], af[mt][1], af[mt][2], af[mt][3],
                       &as[(wm + mt * 16 + rowA) * SKH + kb + kselA]);
            #pragma unroll
            for (int p = 0; p < 2; p++)
                ldm_x4(bf[2*p][0], bf[2*p][1], bf[2*p+1][0], bf[2*p+1][1],
                       &bs[(wn + p * 16 + nselB + rowB) * SKH + kb + kselB]);
            #pragma unroll
            for (int mt = 0; mt < 4; mt++)
                #pragma unroll
                for (int nt = 0; nt < 4; nt++)
                    mma_fp16(acc[mt][nt], af[mt], bf[nt]);
        }
        __syncthreads();
    }

    // Epilogue: c0:(g,2t) c1:(g,2t+1) c2:(g+8,2t) c3:(g+8,2t+1)
    #pragma unroll
    for (int mt = 0; mt < 4; mt++) {
        int r = m0 + wm + mt * 16 + g;
        #pragma unroll
        for (int nt = 0; nt < 4; nt++) {
            int c = n0 + wn + nt * 8 + 2 * t;
            float b0 = 0.f, b1 = 0.f;
            if (HAS_BIAS) { b0 = bias[c]; b1 = bias[c + 1]; }
            *(float2*)&C[(size_t)(r    ) * ldc + c] = make_float2(acc[mt][nt][0] + b0, acc[mt][nt][1] + b1);
            *(float2*)&C[(size_t)(r + 8) * ldc + c] = make_float2(acc[mt][nt][2] + b0, acc[mt][nt][3] + b1);
        }
    }
}

// ---------------------------------------------------------------------------
// K2: attention. One warp per (b,l,h). 5-tap gather from PROJ, softmax,
// weighted V sum, /sqrt(64) -> fp16 ATTN.
// Out-of-range taps: content zero => k/v collapse to biases.
// ---------------------------------------------------------------------------
__global__ __launch_bounds__(256) void attn_kernel(const float* __restrict__ qb,
                                                   const float* __restrict__ kb,
                                                   const float* __restrict__ vb) {
    int w    = (blockIdx.x * blockDim.x + threadIdx.x) >> 5;
    int lane = threadIdx.x & 31;
    if (w >= MTOT * HH) return;

    int h   = w & 7;
    int row = w >> 3;                 // = b*LL + l
    int l   = row & (LL - 1);
    int b   = row >> 11;
    int d   = 1 << (h & 3);           // dilations {1,2,4,8,1,2,4,8}

    const float* P = g_PROJ;
    size_t rq = (size_t)row * NTOT;
    int qoff = h * HW;
    float q0 = P[rq + qoff + lane]      + qb[qoff + lane];
    float q1 = P[rq + qoff + lane + 32] + qb[qoff + lane + 32];

    float lg[KT], v0[KT], v1[KT];
    #pragma unroll
    for (int kk = 0; kk < KT; ++kk) {
        int sl   = l + (kk - 2) * d;
        int kidx = (h * KT + kk) * HW;
        float kv0, kv1;
        if (sl >= 0 && sl < LL) {
            size_t rr = (size_t)(b * LL + sl) * NTOT;
            kv0    = P[rr + KBASE + kidx + lane]      + kb[kidx + lane];
            kv1    = P[rr + KBASE + kidx + lane + 32] + kb[kidx + lane + 32];
            v0[kk] = P[rr + VBASE + kidx + lane]      + vb[kidx + lane];
            v1[kk] = P[rr + VBASE + kidx + lane + 32] + vb[kidx + lane + 32];
        } else {
            kv0    = kb[kidx + lane];      kv1    = kb[kidx + lane + 32];
            v0[kk] = vb[kidx + lane];      v1[kk] = vb[kidx + lane + 32];
        }
        float p = q0 * kv0 + q1 * kv1;
        #pragma unroll
        for (int s = 16; s > 0; s >>= 1) p += __shfl_xor_sync(0xffffffffu, p, s);
        lg[kk] = p;
    }

    float mx = lg[0];
    #pragma unroll
    for (int kk = 1; kk < KT; ++kk) mx = fmaxf(mx, lg[kk]);
    float e[KT], se = 0.f;
    #pragma unroll
    for (int kk = 0; kk < KT; ++kk) { e[kk] = __expf(lg[kk] - mx); se += e[kk]; }
    float inv = 1.f / se;

    float a0 = 0.f, a1 = 0.f;
    #pragma unroll
    for (int kk = 0; kk < KT; ++kk) { a0 += e[kk] * v0[kk]; a1 += e[kk] * v1[kk]; }
    a0 *= inv * 0.125f;   // / sqrt(HEAD_W)
    a1 *= inv * 0.125f;

    g_ATTN[(size_t)row * DM + qoff + lane]      = __float2half_rn(a0);
    g_ATTN[(size_t)row * DM + qoff + lane + 32] = __float2half_rn(a1);
}

// ---------------------------------------------------------------------------
// Launch
// ---------------------------------------------------------------------------
extern "C" void kernel_launch(void* const* d_in, const int* in_sizes, int n_in,
                              void* d_out, int out_size) {
    const float* x   = (const float*)d_in[0];
    const float* q_w = (const float*)d_in[1];
    const float* q_b = (const float*)d_in[2];
    const float* k_w = (const float*)d_in[3];
    const float* k_b = (const float*)d_in[4];
    const float* v_w = (const float*)d_in[5];
    const float* v_b = (const float*)d_in[6];
    const float* o_w = (const float*)d_in[7];
    const float* o_b = (const float*)d_in[8];

    __half *Xh, *Wh, *OWh, *ATTN;
    float *PROJ;
    cudaGetSymbolAddress((void**)&Xh,   g_Xh);
    cudaGetSymbolAddress((void**)&Wh,   g_Wh);
    cudaGetSymbolAddress((void**)&OWh,  g_OWh);
    cudaGetSymbolAddress((void**)&PROJ, g_PROJ);
    cudaGetSymbolAddress((void**)&ATTN, g_ATTN);

    // K0: convert to fp16
    prep_kernel<<<(PREP_TOT + 255) / 256, 256>>>(x, q_w, k_w, v_w, o_w);

    // K1: PROJ[4096, 5632] = Xh @ Wh^T  (fp16 MMA, fp32 accum)
    gemm_fp16<false><<<dim3(NTOT / BN, MTOT / BM), 256>>>(Xh, Wh, PROJ, NTOT, nullptr);

    // K2: attention -> ATTN[4096, 512] (fp16)
    attn_kernel<<<(MTOT * HH * 32) / 256, 256>>>(q_b, k_b, v_b);

    // K3: OUT = ATTN @ OWh^T + o_b
    gemm_fp16<true><<<dim3(DM / BN, MTOT / BM), 256>>>(ATTN, OWh, (float*)d_out, DM, o_b);
}